// round 16
// baseline (speedup 1.0000x reference)
#include <cuda_runtime.h>
#include <cuda_fp16.h>

#define N_NODES  50000
#define SLOTS    96
#define HID      128
#define IN_DIM   64
#define OUT_DIM  10
#define N_GRAPHS 64

// ---------------- scratch (device globals; referenced ONLY in device code) ---
// row N_NODES (and +7 spare) is a permanent zero row used as gather padding.
__device__ int    g_cnt_i[N_NODES];
__device__ int    g_slots[(size_t)N_NODES * SLOTS];
__device__ __align__(16) unsigned char g_xs8[(size_t)(N_NODES + 8) * IN_DIM]; // fp8 dinv*x
__device__ __align__(16) unsigned char g_h18[(size_t)(N_NODES + 8) * HID];    // fp8 gemm1 out
__device__ __half g_y1h[(size_t)(N_NODES + 8) * IN_DIM];  // agg1 out / gemm1 in (fp16)
__device__ __half g_y2h[(size_t)(N_NODES + 8) * HID];     // agg2 out / gemm2 in (fp16)
__device__ __half g_h2h[(size_t)N_NODES * HID];           // gemm2 out (relu, fp16)
__device__ __half g_w1h[HID * IN_DIM];
__device__ __half g_w2h[HID * HID];
__device__ float  g_pool[N_GRAPHS * HID];
__device__ float  g_cnt[N_GRAPHS];

// ---------------- PTX helpers -------------------------------------------------
__device__ __forceinline__ unsigned s2u(const void* p) {
    unsigned a;
    asm("{ .reg .u64 t; cvta.to.shared.u64 t, %1; cvt.u32.u64 %0, t; }"
        : "=r"(a) : "l"(p));
    return a;
}

__device__ __forceinline__ void ldsm4(unsigned* r, unsigned addr) {
    asm volatile("ldmatrix.sync.aligned.m8n8.x4.shared.b16 {%0,%1,%2,%3}, [%4];"
                 : "=r"(r[0]), "=r"(r[1]), "=r"(r[2]), "=r"(r[3]) : "r"(addr));
}

__device__ __forceinline__ void mma16816(float* d, const unsigned* a,
                                         unsigned b0, unsigned b1) {
    asm volatile(
        "mma.sync.aligned.m16n8k16.row.col.f32.f16.f16.f32 "
        "{%0,%1,%2,%3}, {%4,%5,%6,%7}, {%8,%9}, {%0,%1,%2,%3};"
        : "+f"(d[0]), "+f"(d[1]), "+f"(d[2]), "+f"(d[3])
        : "r"(a[0]), "r"(a[1]), "r"(a[2]), "r"(a[3]), "r"(b0), "r"(b1));
}

// fp8x16 accumulate: one LDG.128 + 4 splits + 8 cvt + 8 HADD2 (16 values)
__device__ __forceinline__ void acc_f8(__half2* a, const unsigned char* p) {
    uint4 u = *(const uint4*)p;
    unsigned short s[8];
    asm("mov.b32 {%0,%1}, %2;" : "=h"(s[0]), "=h"(s[1]) : "r"(u.x));
    asm("mov.b32 {%0,%1}, %2;" : "=h"(s[2]), "=h"(s[3]) : "r"(u.y));
    asm("mov.b32 {%0,%1}, %2;" : "=h"(s[4]), "=h"(s[5]) : "r"(u.z));
    asm("mov.b32 {%0,%1}, %2;" : "=h"(s[6]), "=h"(s[7]) : "r"(u.w));
#pragma unroll
    for (int j = 0; j < 8; j++) {
        unsigned r;
        asm("cvt.rn.f16x2.e4m3x2 %0, %1;" : "=r"(r) : "h"(s[j]));
        a[j] = __hadd2(a[j], *(__half2*)&r);
    }
}

__device__ __forceinline__ void acc_h4(float* a, const __half* p) {
    uint2 u = *(const uint2*)p;
    float2 f0 = __half22float2(*(__half2*)&u.x);
    float2 f1 = __half22float2(*(__half2*)&u.y);
    a[0] += f0.x; a[1] += f0.y; a[2] += f1.x; a[3] += f1.y;
}

__device__ __forceinline__ float node_dinv(int n) {
    return rsqrtf((float)g_cnt_i[n] + 1.0f);
}

// two f32 -> packed e4m3x2 (lo = first arg position b, hi = a)
__device__ __forceinline__ unsigned short f32x2_to_e4m3x2(float lo, float hi) {
    unsigned short s;
    asm("cvt.rn.satfinite.e4m3x2.f32 %0, %1, %2;" : "=h"(s) : "f"(hi), "f"(lo));
    return s;
}

// ---------------- init (+ weight conversion) ----------------------------------
__global__ void init_kernel(const float* __restrict__ w1,
                            const float* __restrict__ w2) {
    int i = blockIdx.x * blockDim.x + threadIdx.x;
    if (i < N_NODES) g_cnt_i[i] = 0;
    if (i < N_GRAPHS * HID) g_pool[i] = 0.0f;
    if (i < N_GRAPHS) g_cnt[i] = 0.0f;
    if (i < 8 * IN_DIM) g_xs8[(size_t)N_NODES * IN_DIM + i] = 0;
    if (i < 8 * HID)    g_h18[(size_t)N_NODES * HID + i] = 0;
    if (i < HID * IN_DIM) g_w1h[i] = __float2half(w1[i]);
    if (i < HID * HID)    g_w2h[i] = __float2half(w2[i]);
}

// one fused pass: degree count + bucket fill (8 edges per thread, int4 loads)
__global__ void build_kernel(const int* __restrict__ ei, int E) {
    int i = (blockIdx.x * blockDim.x + threadIdx.x) * 8;
    if (i >= E) return;
    if (i + 7 < E) {
        int4 s0 = *(const int4*)(ei + i);
        int4 s1 = *(const int4*)(ei + i + 4);
        int4 d0 = *(const int4*)(ei + E + i);
        int4 d1 = *(const int4*)(ei + E + i + 4);
        int p0 = atomicAdd(&g_cnt_i[d0.x], 1);
        int p1 = atomicAdd(&g_cnt_i[d0.y], 1);
        int p2 = atomicAdd(&g_cnt_i[d0.z], 1);
        int p3 = atomicAdd(&g_cnt_i[d0.w], 1);
        int p4 = atomicAdd(&g_cnt_i[d1.x], 1);
        int p5 = atomicAdd(&g_cnt_i[d1.y], 1);
        int p6 = atomicAdd(&g_cnt_i[d1.z], 1);
        int p7 = atomicAdd(&g_cnt_i[d1.w], 1);
        if (p0 < SLOTS) g_slots[(size_t)d0.x * SLOTS + p0] = s0.x;
        if (p1 < SLOTS) g_slots[(size_t)d0.y * SLOTS + p1] = s0.y;
        if (p2 < SLOTS) g_slots[(size_t)d0.z * SLOTS + p2] = s0.z;
        if (p3 < SLOTS) g_slots[(size_t)d0.w * SLOTS + p3] = s0.w;
        if (p4 < SLOTS) g_slots[(size_t)d1.x * SLOTS + p4] = s1.x;
        if (p5 < SLOTS) g_slots[(size_t)d1.y * SLOTS + p5] = s1.y;
        if (p6 < SLOTS) g_slots[(size_t)d1.z * SLOTS + p6] = s1.z;
        if (p7 < SLOTS) g_slots[(size_t)d1.w * SLOTS + p7] = s1.w;
    } else {
        for (int j = i; j < E; j++) {
            int s = ei[j], d = ei[E + j];
            int p = atomicAdd(&g_cnt_i[d], 1);
            if (p < SLOTS) g_slots[(size_t)d * SLOTS + p] = s;
        }
    }
}

// g_xs8 = e4m3(dinv * x)
__global__ void scale_x_kernel(const float* __restrict__ x) {
    int idx = blockIdx.x * blockDim.x + threadIdx.x;   // float4 index
    if (idx >= N_NODES * (IN_DIM / 4)) return;
    int n = idx >> 4;
    float dv = node_dinv(n);
    float4 v = ((const float4*)x)[idx];
    unsigned short s0 = f32x2_to_e4m3x2(v.x * dv, v.y * dv);
    unsigned short s1 = f32x2_to_e4m3x2(v.z * dv, v.w * dv);
    unsigned o;
    asm("mov.b32 %0, {%1,%2};" : "=r"(o) : "h"(s0), "h"(s1));
    *(unsigned*)(g_xs8 + (size_t)n * IN_DIM + (idx & 15) * 4) = o;
}

// ---------------- layer-1 aggregation (64-dim fp8) ---------------------------
// 16 lanes per node; 4 subs of 4 lanes, each sub one edge (uint4 = 16 fp8/lane).
__global__ void __launch_bounds__(256) agg1_kernel() {
    int gid = blockIdx.x * blockDim.x + threadIdx.x;
    int node = gid >> 4;
    if (node >= N_NODES) return;
    int lane16 = threadIdx.x & 15;
    int sub = lane16 >> 2;          // 0..3
    int colb = (lane16 & 3) * 16;   // byte offset within 64-B row

    const unsigned char* __restrict__ xs = g_xs8;
    __half2 z = __half2half2(__ushort_as_half(0));
    __half2 a[8] = {z, z, z, z, z, z, z, z};
    if (sub == 0)
        acc_f8(a, xs + (size_t)node * IN_DIM + colb);   // self term

    int cnt_full = g_cnt_i[node];
    int cnt = min(cnt_full, SLOTS);
    const int* bucket = g_slots + (size_t)node * SLOTS;

    int b = 0;
#pragma unroll 2
    for (; b + 4 <= cnt; b += 4) {
        int4 q = *(const int4*)(bucket + b);
        int ea = (sub & 2) ? q.z : q.x;
        int eb = (sub & 2) ? q.w : q.y;
        int e  = (sub & 1) ? eb : ea;
        acc_f8(a, xs + (size_t)e * IN_DIM + colb);
    }
    if (b < cnt) {                                      // remainder, guarded
        int4 q = *(const int4*)(bucket + b);
        q.y = (b + 1 < cnt) ? q.y : N_NODES;
        q.z = (b + 2 < cnt) ? q.z : N_NODES;
        q.w = (b + 3 < cnt) ? q.w : N_NODES;
        int ea = (sub & 2) ? q.z : q.x;
        int eb = (sub & 2) ? q.w : q.y;
        int e  = (sub & 1) ? eb : ea;
        acc_f8(a, xs + (size_t)e * IN_DIM + colb);
    }
    // combine 4 subs (xor 4, then 8 — stays within the 16-lane group)
#pragma unroll
    for (int j = 0; j < 8; j++) {
        unsigned v = *(unsigned*)&a[j];
        unsigned o4 = __shfl_xor_sync(0xFFFFFFFFu, v, 4);
        a[j] = __hadd2(a[j], *(__half2*)&o4);
        unsigned v2 = *(unsigned*)&a[j];
        unsigned o8 = __shfl_xor_sync(0xFFFFFFFFu, v2, 8);
        a[j] = __hadd2(a[j], *(__half2*)&o8);
    }
    if (sub == 0) {
        float dv = rsqrtf((float)cnt_full + 1.0f);
        uint4 o0, o1;
        unsigned* p0 = (unsigned*)&o0;
        unsigned* p1 = (unsigned*)&o1;
#pragma unroll
        for (int j = 0; j < 4; j++) {
            float2 f = __half22float2(a[j]);
            *(__half2*)&p0[j] = __floats2half2_rn(f.x * dv, f.y * dv);
            float2 g = __half22float2(a[j + 4]);
            *(__half2*)&p1[j] = __floats2half2_rn(g.x * dv, g.y * dv);
        }
        __half* dst = g_y1h + (size_t)node * IN_DIM + (lane16 & 3) * 16;
        *(uint4*)dst = o0;
        *(uint4*)(dst + 8) = o1;
    }
}

// ---------------- layer-2 aggregation (128-dim fp8) --------------------------
// 32 lanes per node; 4 subs of 8 lanes, each sub one edge (uint4 = 16 fp8/lane).
__global__ void __launch_bounds__(256) agg2_kernel() {
    int warp = (blockIdx.x * blockDim.x + threadIdx.x) >> 5;
    if (warp >= N_NODES) return;
    int lane = threadIdx.x & 31;
    int sub = lane >> 3;            // 0..3
    int colb = (lane & 7) * 16;     // byte offset within 128-B row

    const unsigned char* __restrict__ hs = g_h18;
    __half2 z = __half2half2(__ushort_as_half(0));
    __half2 a[8] = {z, z, z, z, z, z, z, z};
    if (sub == 0)
        acc_f8(a, hs + (size_t)warp * HID + colb);      // self term

    int cnt_full = g_cnt_i[warp];
    int cnt = min(cnt_full, SLOTS);
    const int* bucket = g_slots + (size_t)warp * SLOTS;

    int b = 0;
#pragma unroll 2
    for (; b + 4 <= cnt; b += 4) {
        int4 q = *(const int4*)(bucket + b);
        int ea = (sub & 2) ? q.z : q.x;
        int eb = (sub & 2) ? q.w : q.y;
        int e  = (sub & 1) ? eb : ea;
        acc_f8(a, hs + (size_t)e * HID + colb);
    }
    if (b < cnt) {                                      // remainder, guarded
        int4 q = *(const int4*)(bucket + b);
        q.y = (b + 1 < cnt) ? q.y : N_NODES;
        q.z = (b + 2 < cnt) ? q.z : N_NODES;
        q.w = (b + 3 < cnt) ? q.w : N_NODES;
        int ea = (sub & 2) ? q.z : q.x;
        int eb = (sub & 2) ? q.w : q.y;
        int e  = (sub & 1) ? eb : ea;
        acc_f8(a, hs + (size_t)e * HID + colb);
    }
    // combine 4 subs (xor 8, then 16)
#pragma unroll
    for (int j = 0; j < 8; j++) {
        unsigned v = *(unsigned*)&a[j];
        unsigned o8 = __shfl_xor_sync(0xFFFFFFFFu, v, 8);
        a[j] = __hadd2(a[j], *(__half2*)&o8);
        unsigned v2 = *(unsigned*)&a[j];
        unsigned o16 = __shfl_xor_sync(0xFFFFFFFFu, v2, 16);
        a[j] = __hadd2(a[j], *(__half2*)&o16);
    }
    if (sub == 0) {
        float dv = rsqrtf((float)cnt_full + 1.0f);
        uint4 o0, o1;
        unsigned* p0 = (unsigned*)&o0;
        unsigned* p1 = (unsigned*)&o1;
#pragma unroll
        for (int j = 0; j < 4; j++) {
            float2 f = __half22float2(a[j]);
            *(__half2*)&p0[j] = __floats2half2_rn(f.x * dv, f.y * dv);
            float2 g = __half22float2(a[j + 4]);
            *(__half2*)&p1[j] = __floats2half2_rn(g.x * dv, g.y * dv);
        }
        __half* dst = g_y2h + (size_t)warp * HID + (lane & 7) * 16;
        *(uint4*)dst = o0;
        *(uint4*)(dst + 8) = o1;
    }
}

// ---------------- HMMA GEMM: 128x128 tile, 8 warps (2m x 4n), warp 64x32 -----
// LAYER2=false: g_h18[row] = e4m3(dinv[row] * relu(y1h W1^T + b))   (K=64)
// LAYER2=true : g_h2h[row] = half(relu(y2h W2^T + b))               (K=128)
template <int K, bool LAYER2>
__global__ void __launch_bounds__(256) hgemm_kernel(const float* __restrict__ bias) {
    const __half* __restrict__ Xin = LAYER2 ? g_y2h : g_y1h;
    const __half* __restrict__ Wh  = LAYER2 ? g_w2h : g_w1h;

    __shared__ __half As[128][40];   // 40-half row stride avoids ldmatrix conflicts
    __shared__ __half Bs[128][40];

    int tid = threadIdx.x;
    int warp = tid >> 5, l = tid & 31;
    int wm = warp >> 2, wn = warp & 3;
    int row0 = blockIdx.x * 128;

    float d[4][4][4];
#pragma unroll
    for (int i = 0; i < 4; i++)
#pragma unroll
        for (int j = 0; j < 4; j++)
#pragma unroll
            for (int r = 0; r < 4; r++) d[i][j][r] = 0.f;

    int rowA = (l & 7) + ((l & 8) ? 8 : 0);
    int colA = (l & 16) ? 8 : 0;
    int rowB = (l & 7) + ((l & 16) ? 8 : 0);
    int colB = (l & 8) ? 8 : 0;
    unsigned a_base = s2u(&As[0][0]);
    unsigned b_base = s2u(&Bs[0][0]);

    for (int kc = 0; kc < K; kc += 32) {
#pragma unroll
        for (int j = 0; j < 2; j++) {
            int idx = tid + j * 256;
            int r = idx >> 2, ch = idx & 3;
            int gr = row0 + r;
            uint4 val = make_uint4(0, 0, 0, 0);
            if (gr < N_NODES)
                val = *(const uint4*)(Xin + (size_t)gr * K + kc + ch * 8);
            *(uint4*)&As[r][ch * 8] = val;
            *(uint4*)&Bs[r][ch * 8] = *(const uint4*)(Wh + r * K + kc + ch * 8);
        }
        __syncthreads();

#pragma unroll
        for (int k16 = 0; k16 < 32; k16 += 16) {
            unsigned bfrag[2][4];
#pragma unroll
            for (int jn = 0; jn < 2; jn++) {
                unsigned addr = b_base +
                    (unsigned)(((wn * 32 + jn * 16 + rowB) * 40 + k16 + colB) * 2);
                ldsm4(bfrag[jn], addr);
            }
#pragma unroll
            for (int im = 0; im < 4; im++) {
                unsigned afrag[4];
                unsigned addr = a_base +
                    (unsigned)(((wm * 64 + im * 16 + rowA) * 40 + k16 + colA) * 2);
                ldsm4(afrag, addr);
                mma16816(d[im][0], afrag, bfrag[0][0], bfrag[0][1]);
                mma16816(d[im][1], afrag, bfrag[0][2], bfrag[0][3]);
                mma16816(d[im][2], afrag, bfrag[1][0], bfrag[1][1]);
                mma16816(d[im][3], afrag, bfrag[1][2], bfrag[1][3]);
            }
        }
        __syncthreads();
    }

#pragma unroll
    for (int im = 0; im < 4; im++) {
        int r_lo = row0 + wm * 64 + im * 16 + (l >> 2);
        int r_hi = r_lo + 8;
        float dvlo = 1.f, dvhi = 1.f;
        if (!LAYER2) {
            if (r_lo < N_NODES) dvlo = node_dinv(r_lo);
            if (r_hi < N_NODES) dvhi = node_dinv(r_hi);
        }
#pragma unroll
        for (int in = 0; in < 4; in++) {
            int n = wn * 32 + in * 8 + 2 * (l & 3);
            float2 bb = *(const float2*)(bias + n);
            float v0 = fmaxf(d[im][in][0] + bb.x, 0.f) * dvlo;
            float v1 = fmaxf(d[im][in][1] + bb.y, 0.f) * dvlo;
            float v2 = fmaxf(d[im][in][2] + bb.x, 0.f) * dvhi;
            float v3 = fmaxf(d[im][in][3] + bb.y, 0.f) * dvhi;
            if (!LAYER2) {
                if (r_lo < N_NODES)
                    *(unsigned short*)(g_h18 + (size_t)r_lo * HID + n) =
                        f32x2_to_e4m3x2(v0, v1);
                if (r_hi < N_NODES)
                    *(unsigned short*)(g_h18 + (size_t)r_hi * HID + n) =
                        f32x2_to_e4m3x2(v2, v3);
            } else {
                if (r_lo < N_NODES)
                    *(__half2*)(g_h2h + (size_t)r_lo * HID + n) =
                        __floats2half2_rn(v0, v1);
                if (r_hi < N_NODES)
                    *(__half2*)(g_h2h + (size_t)r_hi * HID + n) =
                        __floats2half2_rn(v2, v3);
            }
        }
    }
}

// ---------------- pooling: segmented sum of h2h rows + graph node counts -----
__global__ void pool_kernel(const int* __restrict__ batch) {
    int gw = (blockIdx.x * blockDim.x + threadIdx.x) >> 5;
    int n0 = gw * 32;
    if (n0 >= N_NODES) return;
    int lane = threadIdx.x & 31;
    int n1 = min(n0 + 32, N_NODES);

    float a[4] = {0.f, 0.f, 0.f, 0.f};
    float c = 0.f;
    int cur = __ldg(batch + n0);
    for (int n = n0; n < n1; n++) {
        int g = __ldg(batch + n);
        if (g != cur) {
            float* dst = g_pool + (size_t)cur * HID + lane * 4;
            asm volatile("red.global.add.v4.f32 [%0], {%1, %2, %3, %4};"
                         :: "l"(dst), "f"(a[0]), "f"(a[1]), "f"(a[2]), "f"(a[3])
                         : "memory");
            if (lane == 0) atomicAdd(&g_cnt[cur], c);
            a[0] = a[1] = a[2] = a[3] = 0.f;
            c = 0.f;
            cur = g;
        }
        acc_h4(a, g_h2h + (size_t)n * HID + lane * 4);
        c += 1.f;
    }
    float* dst = g_pool + (size_t)cur * HID + lane * 4;
    asm volatile("red.global.add.v4.f32 [%0], {%1, %2, %3, %4};"
                 :: "l"(dst), "f"(a[0]), "f"(a[1]), "f"(a[2]), "f"(a[3])
                 : "memory");
    if (lane == 0) atomicAdd(&g_cnt[cur], c);
}

// ---------------- final: out[g][o] = pooled[g]/cnt . fc_w[o] + fc_b[o] -------
__global__ void final_kernel(const float* __restrict__ fcw,
                             const float* __restrict__ fcb,
                             float* __restrict__ out) {
    int g = blockIdx.x;
    int lane = threadIdx.x;
    float inv = 1.0f / fmaxf(g_cnt[g], 1.0f);
    float p[4];
#pragma unroll
    for (int j = 0; j < 4; j++) p[j] = g_pool[g * HID + j * 32 + lane] * inv;
#pragma unroll
    for (int o = 0; o < OUT_DIM; o++) {
        float s = 0.0f;
#pragma unroll
        for (int j = 0; j < 4; j++) s += p[j] * fcw[o * HID + j * 32 + lane];
#pragma unroll
        for (int off = 16; off; off >>= 1) s += __shfl_down_sync(0xFFFFFFFFu, s, off);
        if (lane == 0) out[g * OUT_DIM + o] = s + fcb[o];
    }
}

// ---------------- launch ------------------------------------------------------
extern "C" void kernel_launch(void* const* d_in, const int* in_sizes, int n_in,
                              void* d_out, int out_size) {
    const float* x     = (const float*)d_in[0];
    const int*   ei    = (const int*)  d_in[1];
    const int*   batch = (const int*)  d_in[2];
    const float* w1    = (const float*)d_in[3];
    const float* b1    = (const float*)d_in[4];
    const float* w2    = (const float*)d_in[5];
    const float* b2    = (const float*)d_in[6];
    const float* fcw   = (const float*)d_in[7];
    const float* fcb   = (const float*)d_in[8];
    float* out = (float*)d_out;
    int E = in_sizes[1] / 2;

    int nblk = (N_NODES + 255) / 256;
    int eblk8 = (E / 8 + 255) / 256;
    int gemm_blocks = (N_NODES + 127) / 128;

    init_kernel<<<nblk, 256>>>(w1, w2);
    build_kernel<<<eblk8, 256>>>(ei, E);
    scale_x_kernel<<<(N_NODES * 16 + 255) / 256, 256>>>(x);

    // layer 1
    agg1_kernel<<<(N_NODES * 16 + 255) / 256, 256>>>();
    hgemm_kernel<IN_DIM, false><<<gemm_blocks, 256>>>(b1);

    // layer 2
    agg2_kernel<<<(N_NODES * 32 + 255) / 256, 256>>>();
    hgemm_kernel<HID, true><<<gemm_blocks, 256>>>(b2);

    pool_kernel<<<nblk, 256>>>(batch);
    final_kernel<<<N_GRAPHS, 32>>>(fcw, fcb, out);
}

// round 17
// speedup vs baseline: 1.0642x; 1.0642x over previous
#include <cuda_runtime.h>
#include <cuda_fp16.h>

#define N_NODES  50000
#define SLOTS    96
#define HID      128
#define IN_DIM   64
#define OUT_DIM  10
#define N_GRAPHS 64

// ---------------- scratch (device globals; referenced ONLY in device code) ---
// row N_NODES (and +7 spare) is a permanent zero row used as gather padding.
__device__ int    g_cnt_i[N_NODES];
__device__ int    g_slots[(size_t)N_NODES * SLOTS];
__device__ __align__(16) unsigned char g_xs8[(size_t)(N_NODES + 8) * IN_DIM]; // fp8 dinv*x
__device__ __align__(16) unsigned char g_h18[(size_t)(N_NODES + 8) * HID];    // fp8 gemm1 out
__device__ __half g_y1h[(size_t)(N_NODES + 8) * IN_DIM];  // agg1 out / gemm1 in (fp16)
__device__ __half g_y2h[(size_t)(N_NODES + 8) * HID];     // agg2 out / gemm2 in (fp16)
__device__ __half g_h2h[(size_t)N_NODES * HID];           // gemm2 out (relu, fp16)
__device__ __half g_w1h[HID * IN_DIM];
__device__ __half g_w2h[HID * HID];
__device__ float  g_pool[N_GRAPHS * HID];
__device__ float  g_cnt[N_GRAPHS];

// ---------------- PTX helpers -------------------------------------------------
__device__ __forceinline__ unsigned s2u(const void* p) {
    unsigned a;
    asm("{ .reg .u64 t; cvta.to.shared.u64 t, %1; cvt.u32.u64 %0, t; }"
        : "=r"(a) : "l"(p));
    return a;
}

__device__ __forceinline__ void ldsm4(unsigned* r, unsigned addr) {
    asm volatile("ldmatrix.sync.aligned.m8n8.x4.shared.b16 {%0,%1,%2,%3}, [%4];"
                 : "=r"(r[0]), "=r"(r[1]), "=r"(r[2]), "=r"(r[3]) : "r"(addr));
}

__device__ __forceinline__ void mma16816(float* d, const unsigned* a,
                                         unsigned b0, unsigned b1) {
    asm volatile(
        "mma.sync.aligned.m16n8k16.row.col.f32.f16.f16.f32 "
        "{%0,%1,%2,%3}, {%4,%5,%6,%7}, {%8,%9}, {%0,%1,%2,%3};"
        : "+f"(d[0]), "+f"(d[1]), "+f"(d[2]), "+f"(d[3])
        : "r"(a[0]), "r"(a[1]), "r"(a[2]), "r"(a[3]), "r"(b0), "r"(b1));
}

// fp8x16 accumulate: one LDG.128 + 4 splits + 8 cvt + 8 HADD2 (16 values)
__device__ __forceinline__ void acc_f8(__half2* a, const unsigned char* p) {
    uint4 u = *(const uint4*)p;
    unsigned short s[8];
    asm("mov.b32 {%0,%1}, %2;" : "=h"(s[0]), "=h"(s[1]) : "r"(u.x));
    asm("mov.b32 {%0,%1}, %2;" : "=h"(s[2]), "=h"(s[3]) : "r"(u.y));
    asm("mov.b32 {%0,%1}, %2;" : "=h"(s[4]), "=h"(s[5]) : "r"(u.z));
    asm("mov.b32 {%0,%1}, %2;" : "=h"(s[6]), "=h"(s[7]) : "r"(u.w));
#pragma unroll
    for (int j = 0; j < 8; j++) {
        unsigned r;
        asm("cvt.rn.f16x2.e4m3x2 %0, %1;" : "=r"(r) : "h"(s[j]));
        a[j] = __hadd2(a[j], *(__half2*)&r);
    }
}

__device__ __forceinline__ void acc_h4(float* a, const __half* p) {
    uint2 u = *(const uint2*)p;
    float2 f0 = __half22float2(*(__half2*)&u.x);
    float2 f1 = __half22float2(*(__half2*)&u.y);
    a[0] += f0.x; a[1] += f0.y; a[2] += f1.x; a[3] += f1.y;
}

__device__ __forceinline__ float node_dinv(int n) {
    return rsqrtf((float)g_cnt_i[n] + 1.0f);
}

// two f32 -> packed e4m3x2
__device__ __forceinline__ unsigned short f32x2_to_e4m3x2(float lo, float hi) {
    unsigned short s;
    asm("cvt.rn.satfinite.e4m3x2.f32 %0, %1, %2;" : "=h"(s) : "f"(hi), "f"(lo));
    return s;
}

// ---------------- init (+ weight conversion) ----------------------------------
__global__ void init_kernel(const float* __restrict__ w1,
                            const float* __restrict__ w2) {
    int i = blockIdx.x * blockDim.x + threadIdx.x;
    if (i < N_NODES) g_cnt_i[i] = 0;
    if (i < N_GRAPHS * HID) g_pool[i] = 0.0f;
    if (i < N_GRAPHS) g_cnt[i] = 0.0f;
    if (i < 8 * IN_DIM) g_xs8[(size_t)N_NODES * IN_DIM + i] = 0;
    if (i < 8 * HID)    g_h18[(size_t)N_NODES * HID + i] = 0;
    if (i < HID * IN_DIM) g_w1h[i] = __float2half(w1[i]);
    if (i < HID * HID)    g_w2h[i] = __float2half(w2[i]);
}

// one fused pass: degree count + bucket fill (8 edges per thread, int4 loads)
__global__ void build_kernel(const int* __restrict__ ei, int E) {
    int i = (blockIdx.x * blockDim.x + threadIdx.x) * 8;
    if (i >= E) return;
    if (i + 7 < E) {
        int4 s0 = *(const int4*)(ei + i);
        int4 s1 = *(const int4*)(ei + i + 4);
        int4 d0 = *(const int4*)(ei + E + i);
        int4 d1 = *(const int4*)(ei + E + i + 4);
        int p0 = atomicAdd(&g_cnt_i[d0.x], 1);
        int p1 = atomicAdd(&g_cnt_i[d0.y], 1);
        int p2 = atomicAdd(&g_cnt_i[d0.z], 1);
        int p3 = atomicAdd(&g_cnt_i[d0.w], 1);
        int p4 = atomicAdd(&g_cnt_i[d1.x], 1);
        int p5 = atomicAdd(&g_cnt_i[d1.y], 1);
        int p6 = atomicAdd(&g_cnt_i[d1.z], 1);
        int p7 = atomicAdd(&g_cnt_i[d1.w], 1);
        if (p0 < SLOTS) g_slots[(size_t)d0.x * SLOTS + p0] = s0.x;
        if (p1 < SLOTS) g_slots[(size_t)d0.y * SLOTS + p1] = s0.y;
        if (p2 < SLOTS) g_slots[(size_t)d0.z * SLOTS + p2] = s0.z;
        if (p3 < SLOTS) g_slots[(size_t)d0.w * SLOTS + p3] = s0.w;
        if (p4 < SLOTS) g_slots[(size_t)d1.x * SLOTS + p4] = s1.x;
        if (p5 < SLOTS) g_slots[(size_t)d1.y * SLOTS + p5] = s1.y;
        if (p6 < SLOTS) g_slots[(size_t)d1.z * SLOTS + p6] = s1.z;
        if (p7 < SLOTS) g_slots[(size_t)d1.w * SLOTS + p7] = s1.w;
    } else {
        for (int j = i; j < E; j++) {
            int s = ei[j], d = ei[E + j];
            int p = atomicAdd(&g_cnt_i[d], 1);
            if (p < SLOTS) g_slots[(size_t)d * SLOTS + p] = s;
        }
    }
}

// g_xs8 = e4m3(dinv * x)
__global__ void scale_x_kernel(const float* __restrict__ x) {
    int idx = blockIdx.x * blockDim.x + threadIdx.x;   // float4 index
    if (idx >= N_NODES * (IN_DIM / 4)) return;
    int n = idx >> 4;
    float dv = node_dinv(n);
    float4 v = ((const float4*)x)[idx];
    unsigned short s0 = f32x2_to_e4m3x2(v.x * dv, v.y * dv);
    unsigned short s1 = f32x2_to_e4m3x2(v.z * dv, v.w * dv);
    unsigned o;
    asm("mov.b32 %0, {%1,%2};" : "=r"(o) : "h"(s0), "h"(s1));
    *(unsigned*)(g_xs8 + (size_t)n * IN_DIM + (idx & 15) * 4) = o;
}

// ---------------- layer-1 aggregation (64-dim fp8) ---------------------------
__global__ void __launch_bounds__(256) agg1_kernel() {
    int gid = blockIdx.x * blockDim.x + threadIdx.x;
    int node = gid >> 4;
    if (node >= N_NODES) return;
    int lane16 = threadIdx.x & 15;
    int sub = lane16 >> 2;          // 0..3
    int colb = (lane16 & 3) * 16;   // byte offset within 64-B row

    const unsigned char* __restrict__ xs = g_xs8;
    __half2 z = __half2half2(__ushort_as_half(0));
    __half2 a[8] = {z, z, z, z, z, z, z, z};
    if (sub == 0)
        acc_f8(a, xs + (size_t)node * IN_DIM + colb);   // self term

    int cnt_full = g_cnt_i[node];
    int cnt = min(cnt_full, SLOTS);
    const int* bucket = g_slots + (size_t)node * SLOTS;

    int b = 0;
#pragma unroll 2
    for (; b + 4 <= cnt; b += 4) {
        int4 q = *(const int4*)(bucket + b);
        int ea = (sub & 2) ? q.z : q.x;
        int eb = (sub & 2) ? q.w : q.y;
        int e  = (sub & 1) ? eb : ea;
        acc_f8(a, xs + (size_t)e * IN_DIM + colb);
    }
    if (b < cnt) {                                      // remainder, guarded
        int4 q = *(const int4*)(bucket + b);
        q.y = (b + 1 < cnt) ? q.y : N_NODES;
        q.z = (b + 2 < cnt) ? q.z : N_NODES;
        q.w = (b + 3 < cnt) ? q.w : N_NODES;
        int ea = (sub & 2) ? q.z : q.x;
        int eb = (sub & 2) ? q.w : q.y;
        int e  = (sub & 1) ? eb : ea;
        acc_f8(a, xs + (size_t)e * IN_DIM + colb);
    }
#pragma unroll
    for (int j = 0; j < 8; j++) {
        unsigned v = *(unsigned*)&a[j];
        unsigned o4 = __shfl_xor_sync(0xFFFFFFFFu, v, 4);
        a[j] = __hadd2(a[j], *(__half2*)&o4);
        unsigned v2 = *(unsigned*)&a[j];
        unsigned o8 = __shfl_xor_sync(0xFFFFFFFFu, v2, 8);
        a[j] = __hadd2(a[j], *(__half2*)&o8);
    }
    if (sub == 0) {
        float dv = rsqrtf((float)cnt_full + 1.0f);
        uint4 o0, o1;
        unsigned* p0 = (unsigned*)&o0;
        unsigned* p1 = (unsigned*)&o1;
#pragma unroll
        for (int j = 0; j < 4; j++) {
            float2 f = __half22float2(a[j]);
            *(__half2*)&p0[j] = __floats2half2_rn(f.x * dv, f.y * dv);
            float2 g = __half22float2(a[j + 4]);
            *(__half2*)&p1[j] = __floats2half2_rn(g.x * dv, g.y * dv);
        }
        __half* dst = g_y1h + (size_t)node * IN_DIM + (lane16 & 3) * 16;
        *(uint4*)dst = o0;
        *(uint4*)(dst + 8) = o1;
    }
}

// ---------------- layer-2 aggregation (128-dim fp8) --------------------------
__global__ void __launch_bounds__(256) agg2_kernel() {
    int warp = (blockIdx.x * blockDim.x + threadIdx.x) >> 5;
    if (warp >= N_NODES) return;
    int lane = threadIdx.x & 31;
    int sub = lane >> 3;            // 0..3
    int colb = (lane & 7) * 16;     // byte offset within 128-B row

    const unsigned char* __restrict__ hs = g_h18;
    __half2 z = __half2half2(__ushort_as_half(0));
    __half2 a[8] = {z, z, z, z, z, z, z, z};
    if (sub == 0)
        acc_f8(a, hs + (size_t)warp * HID + colb);      // self term

    int cnt_full = g_cnt_i[warp];
    int cnt = min(cnt_full, SLOTS);
    const int* bucket = g_slots + (size_t)warp * SLOTS;

    int b = 0;
#pragma unroll 2
    for (; b + 4 <= cnt; b += 4) {
        int4 q = *(const int4*)(bucket + b);
        int ea = (sub & 2) ? q.z : q.x;
        int eb = (sub & 2) ? q.w : q.y;
        int e  = (sub & 1) ? eb : ea;
        acc_f8(a, hs + (size_t)e * HID + colb);
    }
    if (b < cnt) {                                      // remainder, guarded
        int4 q = *(const int4*)(bucket + b);
        q.y = (b + 1 < cnt) ? q.y : N_NODES;
        q.z = (b + 2 < cnt) ? q.z : N_NODES;
        q.w = (b + 3 < cnt) ? q.w : N_NODES;
        int ea = (sub & 2) ? q.z : q.x;
        int eb = (sub & 2) ? q.w : q.y;
        int e  = (sub & 1) ? eb : ea;
        acc_f8(a, hs + (size_t)e * HID + colb);
    }
#pragma unroll
    for (int j = 0; j < 8; j++) {
        unsigned v = *(unsigned*)&a[j];
        unsigned o8 = __shfl_xor_sync(0xFFFFFFFFu, v, 8);
        a[j] = __hadd2(a[j], *(__half2*)&o8);
        unsigned v2 = *(unsigned*)&a[j];
        unsigned o16 = __shfl_xor_sync(0xFFFFFFFFu, v2, 16);
        a[j] = __hadd2(a[j], *(__half2*)&o16);
    }
    if (sub == 0) {
        float dv = rsqrtf((float)cnt_full + 1.0f);
        uint4 o0, o1;
        unsigned* p0 = (unsigned*)&o0;
        unsigned* p1 = (unsigned*)&o1;
#pragma unroll
        for (int j = 0; j < 4; j++) {
            float2 f = __half22float2(a[j]);
            *(__half2*)&p0[j] = __floats2half2_rn(f.x * dv, f.y * dv);
            float2 g = __half22float2(a[j + 4]);
            *(__half2*)&p1[j] = __floats2half2_rn(g.x * dv, g.y * dv);
        }
        __half* dst = g_y2h + (size_t)warp * HID + (lane & 7) * 16;
        *(uint4*)dst = o0;
        *(uint4*)(dst + 8) = o1;
    }
}

// ---------------- HMMA GEMM: 128x128 tile, full-K smem (single load phase) ---
// LAYER2=false: g_h18[row] = e4m3(dinv[row] * relu(y1h W1^T + b))   (K=64)
// LAYER2=true : g_h2h[row] = half(relu(y2h W2^T + b))               (K=128)
template <int K, bool LAYER2>
__global__ void __launch_bounds__(256) hgemm_kernel(const float* __restrict__ bias) {
    const int SA = K + 8;   // padded stride in halves (odd multiple of 8)
    const __half* __restrict__ Xin = LAYER2 ? g_y2h : g_y1h;
    const __half* __restrict__ Wh  = LAYER2 ? g_w2h : g_w1h;

    extern __shared__ __half sm[];
    __half* As = sm;                 // [128][SA]
    __half* Bs = sm + 128 * SA;      // [128][SA]

    int tid = threadIdx.x;
    int warp = tid >> 5, l = tid & 31;
    int wm = warp >> 2, wn = warp & 3;
    int row0 = blockIdx.x * 128;

    float d[4][4][4];
#pragma unroll
    for (int i = 0; i < 4; i++)
#pragma unroll
        for (int j = 0; j < 4; j++)
#pragma unroll
            for (int r = 0; r < 4; r++) d[i][j][r] = 0.f;

    // single full-K load phase (8 independent uint4 loads per thread per array)
    const int CH = K / 8;            // 8-half chunks per row
#pragma unroll
    for (int t = tid; t < 128 * CH; t += 256) {
        int r = t / CH, ch = t % CH;
        int gr = row0 + r;
        uint4 val = make_uint4(0, 0, 0, 0);
        if (gr < N_NODES)
            val = *(const uint4*)(Xin + (size_t)gr * K + ch * 8);
        *(uint4*)&As[r * SA + ch * 8] = val;
        *(uint4*)&Bs[r * SA + ch * 8] = *(const uint4*)(Wh + r * K + ch * 8);
    }
    __syncthreads();

    int rowA = (l & 7) + ((l & 8) ? 8 : 0);
    int colA = (l & 16) ? 8 : 0;
    int rowB = (l & 7) + ((l & 16) ? 8 : 0);
    int colB = (l & 8) ? 8 : 0;
    unsigned a_base = s2u(As);
    unsigned b_base = s2u(Bs);

#pragma unroll
    for (int k16 = 0; k16 < K; k16 += 16) {
        unsigned bfrag[2][4];
#pragma unroll
        for (int jn = 0; jn < 2; jn++) {
            unsigned addr = b_base +
                (unsigned)(((wn * 32 + jn * 16 + rowB) * SA + k16 + colB) * 2);
            ldsm4(bfrag[jn], addr);
        }
#pragma unroll
        for (int im = 0; im < 4; im++) {
            unsigned afrag[4];
            unsigned addr = a_base +
                (unsigned)(((wm * 64 + im * 16 + rowA) * SA + k16 + colA) * 2);
            ldsm4(afrag, addr);
            mma16816(d[im][0], afrag, bfrag[0][0], bfrag[0][1]);
            mma16816(d[im][1], afrag, bfrag[0][2], bfrag[0][3]);
            mma16816(d[im][2], afrag, bfrag[1][0], bfrag[1][1]);
            mma16816(d[im][3], afrag, bfrag[1][2], bfrag[1][3]);
        }
    }

#pragma unroll
    for (int im = 0; im < 4; im++) {
        int r_lo = row0 + wm * 64 + im * 16 + (l >> 2);
        int r_hi = r_lo + 8;
        float dvlo = 1.f, dvhi = 1.f;
        if (!LAYER2) {
            if (r_lo < N_NODES) dvlo = node_dinv(r_lo);
            if (r_hi < N_NODES) dvhi = node_dinv(r_hi);
        }
#pragma unroll
        for (int in = 0; in < 4; in++) {
            int n = wn * 32 + in * 8 + 2 * (l & 3);
            float2 bb = *(const float2*)(bias + n);
            float v0 = fmaxf(d[im][in][0] + bb.x, 0.f) * dvlo;
            float v1 = fmaxf(d[im][in][1] + bb.y, 0.f) * dvlo;
            float v2 = fmaxf(d[im][in][2] + bb.x, 0.f) * dvhi;
            float v3 = fmaxf(d[im][in][3] + bb.y, 0.f) * dvhi;
            if (!LAYER2) {
                if (r_lo < N_NODES)
                    *(unsigned short*)(g_h18 + (size_t)r_lo * HID + n) =
                        f32x2_to_e4m3x2(v0, v1);
                if (r_hi < N_NODES)
                    *(unsigned short*)(g_h18 + (size_t)r_hi * HID + n) =
                        f32x2_to_e4m3x2(v2, v3);
            } else {
                if (r_lo < N_NODES)
                    *(__half2*)(g_h2h + (size_t)r_lo * HID + n) =
                        __floats2half2_rn(v0, v1);
                if (r_hi < N_NODES)
                    *(__half2*)(g_h2h + (size_t)r_hi * HID + n) =
                        __floats2half2_rn(v2, v3);
            }
        }
    }
}

// ---------------- pooling: segmented sum of h2h rows + graph node counts -----
__global__ void pool_kernel(const int* __restrict__ batch) {
    int gw = (blockIdx.x * blockDim.x + threadIdx.x) >> 5;
    int n0 = gw * 32;
    if (n0 >= N_NODES) return;
    int lane = threadIdx.x & 31;
    int n1 = min(n0 + 32, N_NODES);

    float a[4] = {0.f, 0.f, 0.f, 0.f};
    float c = 0.f;
    int cur = __ldg(batch + n0);
    for (int n = n0; n < n1; n++) {
        int g = __ldg(batch + n);
        if (g != cur) {
            float* dst = g_pool + (size_t)cur * HID + lane * 4;
            asm volatile("red.global.add.v4.f32 [%0], {%1, %2, %3, %4};"
                         :: "l"(dst), "f"(a[0]), "f"(a[1]), "f"(a[2]), "f"(a[3])
                         : "memory");
            if (lane == 0) atomicAdd(&g_cnt[cur], c);
            a[0] = a[1] = a[2] = a[3] = 0.f;
            c = 0.f;
            cur = g;
        }
        acc_h4(a, g_h2h + (size_t)n * HID + lane * 4);
        c += 1.f;
    }
    float* dst = g_pool + (size_t)cur * HID + lane * 4;
    asm volatile("red.global.add.v4.f32 [%0], {%1, %2, %3, %4};"
                 :: "l"(dst), "f"(a[0]), "f"(a[1]), "f"(a[2]), "f"(a[3])
                 : "memory");
    if (lane == 0) atomicAdd(&g_cnt[cur], c);
}

// ---------------- final: out[g][o] = pooled[g]/cnt . fc_w[o] + fc_b[o] -------
__global__ void final_kernel(const float* __restrict__ fcw,
                             const float* __restrict__ fcb,
                             float* __restrict__ out) {
    int g = blockIdx.x;
    int lane = threadIdx.x;
    float inv = 1.0f / fmaxf(g_cnt[g], 1.0f);
    float p[4];
#pragma unroll
    for (int j = 0; j < 4; j++) p[j] = g_pool[g * HID + j * 32 + lane] * inv;
#pragma unroll
    for (int o = 0; o < OUT_DIM; o++) {
        float s = 0.0f;
#pragma unroll
        for (int j = 0; j < 4; j++) s += p[j] * fcw[o * HID + j * 32 + lane];
#pragma unroll
        for (int off = 16; off; off >>= 1) s += __shfl_down_sync(0xFFFFFFFFu, s, off);
        if (lane == 0) out[g * OUT_DIM + o] = s + fcb[o];
    }
}

// ---------------- launch ------------------------------------------------------
extern "C" void kernel_launch(void* const* d_in, const int* in_sizes, int n_in,
                              void* d_out, int out_size) {
    const float* x     = (const float*)d_in[0];
    const int*   ei    = (const int*)  d_in[1];
    const int*   batch = (const int*)  d_in[2];
    const float* w1    = (const float*)d_in[3];
    const float* b1    = (const float*)d_in[4];
    const float* w2    = (const float*)d_in[5];
    const float* b2    = (const float*)d_in[6];
    const float* fcw   = (const float*)d_in[7];
    const float* fcb   = (const float*)d_in[8];
    float* out = (float*)d_out;
    int E = in_sizes[1] / 2;

    int nblk = (N_NODES + 255) / 256;
    int eblk8 = (E / 8 + 255) / 256;
    int gemm_blocks = (N_NODES + 127) / 128;

    // dynamic smem sizes: 2 arrays of 128 x (K+8) halves
    int smem1 = 2 * 128 * (IN_DIM + 8) * 2;   // 36,864 B
    int smem2 = 2 * 128 * (HID + 8) * 2;      // 69,632 B
    static bool attr_set = false;
    if (!attr_set) {
        cudaFuncSetAttribute(hgemm_kernel<IN_DIM, false>,
                             cudaFuncAttributeMaxDynamicSharedMemorySize, smem1);
        cudaFuncSetAttribute(hgemm_kernel<HID, true>,
                             cudaFuncAttributeMaxDynamicSharedMemorySize, smem2);
        attr_set = true;
    }

    init_kernel<<<nblk, 256>>>(w1, w2);
    build_kernel<<<eblk8, 256>>>(ei, E);
    scale_x_kernel<<<(N_NODES * 16 + 255) / 256, 256>>>(x);

    // layer 1
    agg1_kernel<<<(N_NODES * 16 + 255) / 256, 256>>>();
    hgemm_kernel<IN_DIM, false><<<gemm_blocks, 256, smem1>>>(b1);

    // layer 2
    agg2_kernel<<<(N_NODES * 32 + 255) / 256, 256>>>();
    hgemm_kernel<HID, true><<<gemm_blocks, 256, smem2>>>(b2);

    pool_kernel<<<nblk, 256>>>(batch);
    final_kernel<<<N_GRAPHS, 32>>>(fcw, fcb, out);
}